// round 4
// baseline (speedup 1.0000x reference)
#include <cuda_runtime.h>
#include <math.h>

#define LL1 1024
#define CC 384
#define HH 12
#define PP 128

#define SCALAR_W 0.14433756729740643f
#define POINT_WC 0.13608276348795434f
#define PAIR_W   0.5773502691896258f

#define PROJ 1152
#define FEAT 2112

// ------------- static scratch (no runtime allocation) -------------
__device__ float g_proj[LL1 * PROJ];
__device__ float g_q   [LL1 * 192];
__device__ float g_kT  [HH * 16 * LL1];
__device__ float g_vT  [HH * 16 * LL1];
__device__ float g_qp  [LL1 * 144];
__device__ float g_kpT [HH * 12 * LL1];
__device__ float g_vpT [HH * 24 * LL1];
__device__ float g_sqq [HH * LL1];
__device__ float g_sqk [HH * LL1];
__device__ float g_Z   [(size_t)HH * LL1 * LL1];   // qk logits -> attn (in place)
__device__ float g_feat[(size_t)LL1 * FEAT];

// ------------- K1: projection GEMM X[1024x384] @ W[384x1152] -------------
__device__ __forceinline__ float wload(int r, int gc, const float* Wq,
    const float* Wkv, const float* Wqp, const float* Wkvp) {
  if (gc < 192) return Wq[r * 192 + gc];
  if (gc < 576) return Wkv[r * 384 + (gc - 192)];
  if (gc < 720) return Wqp[r * 144 + (gc - 576)];
  return Wkvp[r * 432 + (gc - 720)];
}

__global__ void k_projgemm(const float* __restrict__ x1d, const float* __restrict__ Wq,
                           const float* __restrict__ Wkv, const float* __restrict__ Wqp,
                           const float* __restrict__ Wkvp) {
  __shared__ float s_x[16][68];
  __shared__ float s_w[16][128];
  int tid = threadIdx.x;
  int tx = tid & 15, ty = tid >> 4;
  int i0 = blockIdx.x * 64, c0 = blockIdx.y * 128;
  float acc[4][8] = {};
  for (int k0 = 0; k0 < CC; k0 += 16) {
    __syncthreads();
    for (int idx = tid; idx < 1024; idx += 256) {
      int il = idx >> 4, kk = idx & 15;
      s_x[kk][il] = x1d[(i0 + il) * CC + k0 + kk];
    }
    for (int idx = tid; idx < 2048; idx += 256) {
      int kk = idx >> 7, cl = idx & 127;
      s_w[kk][cl] = wload(k0 + kk, c0 + cl, Wq, Wkv, Wqp, Wkvp);
    }
    __syncthreads();
#pragma unroll
    for (int kk = 0; kk < 16; kk++) {
      float xv[4], wv[8];
#pragma unroll
      for (int r = 0; r < 4; r++) xv[r] = s_x[kk][ty * 4 + r];
#pragma unroll
      for (int c = 0; c < 8; c++) wv[c] = s_w[kk][tx * 8 + c];
#pragma unroll
      for (int r = 0; r < 4; r++)
#pragma unroll
        for (int c = 0; c < 8; c++) acc[r][c] += xv[r] * wv[c];
    }
  }
#pragma unroll
  for (int r = 0; r < 4; r++)
#pragma unroll
    for (int c = 0; c < 8; c++)
      g_proj[(size_t)(i0 + ty * 4 + r) * PROJ + c0 + tx * 8 + c] = acc[r][c];
}

// ------------- K2: bias/split/rigid/norms per residue -------------
__global__ void k_post(const float* __restrict__ rot, const float* __restrict__ trans,
                       const float* __restrict__ bq, const float* __restrict__ bkv,
                       const float* __restrict__ bqp, const float* __restrict__ bkvp) {
  int i = blockIdx.x, tid = threadIdx.x;
  __shared__ float s_R[9], s_t[3], s_pt[96][3];
  if (tid < 9) s_R[tid] = rot[i * 9 + tid];
  else if (tid < 12) s_t[tid - 9] = trans[i * 3 + tid - 9];
  __syncthreads();
  const float* pr = &g_proj[(size_t)i * PROJ];
  for (int idx = tid; idx < 576; idx += 256) {
    if (idx < 192) {
      g_q[(size_t)i * 192 + idx] = (pr[idx] + bq[idx]) * SCALAR_W;
    } else {
      int m = idx - 192, hh = m >> 5, t = m & 31;
      float v = pr[idx] + bkv[m];
      if (t < 16) g_kT[(hh * 16 + t) * LL1 + i] = v;
      else        g_vT[(hh * 16 + t - 16) * LL1 + i] = v;
    }
  }
  for (int m = tid; m < 192; m += 256) {
    float p0, p1, p2;
    if (m < 48) {
      p0 = pr[576 + m] + bqp[m];
      p1 = pr[624 + m] + bqp[48 + m];
      p2 = pr[672 + m] + bqp[96 + m];
    } else {
      int mm = m - 48;
      p0 = pr[720 + mm] + bkvp[mm];
      p1 = pr[864 + mm] + bkvp[144 + mm];
      p2 = pr[1008 + mm] + bkvp[288 + mm];
    }
    float gx = s_R[0] * p0 + s_R[1] * p1 + s_R[2] * p2 + s_t[0];
    float gy = s_R[3] * p0 + s_R[4] * p1 + s_R[5] * p2 + s_t[1];
    float gz = s_R[6] * p0 + s_R[7] * p1 + s_R[8] * p2 + s_t[2];
    if (m < 48) {
      int hh = m >> 2, n = m & 3;
      size_t b = (size_t)i * 144 + hh * 12 + n * 3;
      g_qp[b] = gx; g_qp[b + 1] = gy; g_qp[b + 2] = gz;
      s_pt[m][0] = gx; s_pt[m][1] = gy; s_pt[m][2] = gz;
    } else {
      int mm = m - 48, hh = mm / 12, t = mm % 12;
      if (t < 4) {
        int b = (hh * 12 + t * 3) * LL1 + i;
        g_kpT[b] = gx; g_kpT[b + LL1] = gy; g_kpT[b + 2 * LL1] = gz;
        int sp = 48 + hh * 4 + t;
        s_pt[sp][0] = gx; s_pt[sp][1] = gy; s_pt[sp][2] = gz;
      } else {
        int b = (hh * 24 + (t - 4) * 3) * LL1 + i;
        g_vpT[b] = gx; g_vpT[b + LL1] = gy; g_vpT[b + 2 * LL1] = gz;
      }
    }
  }
  __syncthreads();
  if (tid < 24) {
    int hh = tid % 12; bool isq = tid < 12;
    float s = 0.f;
#pragma unroll
    for (int n = 0; n < 4; n++) {
      const float* p = s_pt[(isq ? 0 : 48) + hh * 4 + n];
      s += p[0] * p[0] + p[1] * p[1] + p[2] * p[2];
    }
    if (isq) g_sqq[hh * LL1 + i] = s;
    else     g_sqk[hh * LL1 + i] = s;
  }
}

// ------------- K3: qk + dist logits -> g_Z -------------
__global__ void k_qk(const float* __restrict__ tpw) {
  int i0 = blockIdx.x * 8, h = blockIdx.y, tid = threadIdx.x;
  __shared__ float s_q[8][16], s_qp[8][12], s_sqq[8];
  __shared__ float s_pw;
  if (tid < 128) s_q[tid >> 4][tid & 15] = g_q[(size_t)(i0 + (tid >> 4)) * 192 + h * 16 + (tid & 15)];
  else if (tid < 224) { int m = tid - 128; s_qp[m / 12][m % 12] = g_qp[(size_t)(i0 + m / 12) * 144 + h * 12 + m % 12]; }
  else if (tid < 232) s_sqq[tid - 224] = g_sqq[h * LL1 + i0 + tid - 224];
  else if (tid == 232) {
    float x = tpw[h];
    s_pw = -0.5f * POINT_WC * (fmaxf(x, 0.f) + log1pf(expf(-fabsf(x))));
  }
  __syncthreads();
  float pw = s_pw;
  for (int j = tid; j < 1024; j += 256) {
    float kv[16], kp[12];
#pragma unroll
    for (int s = 0; s < 16; s++) kv[s] = g_kT[(h * 16 + s) * LL1 + j];
#pragma unroll
    for (int r = 0; r < 12; r++) kp[r] = g_kpT[(h * 12 + r) * LL1 + j];
    float sqk = g_sqk[h * LL1 + j];
#pragma unroll
    for (int ii = 0; ii < 8; ii++) {
      float d = 0.f, pq = 0.f;
#pragma unroll
      for (int s = 0; s < 16; s++) d += s_q[ii][s] * kv[s];
#pragma unroll
      for (int r = 0; r < 12; r++) pq += s_qp[ii][r] * kp[r];
      g_Z[(size_t)(h * LL1 + i0 + ii) * LL1 + j] = d + pw * (s_sqq[ii] + sqk - 2.f * pq);
    }
  }
}

// ------------- K4: fused pair-bias + softmax + r_2d, block = one i ----------
// smem floats: s_attn[1024*12]=12288, s_A[8192], s_W[1536], s_b[12], s_red[192]
#define FUSE_SMEM_BYTES 118784

__global__ __launch_bounds__(512) void k_fuse(const float* __restrict__ x2d,
                                              const float* __restrict__ Wp,
                                              const float* __restrict__ bp) {
  extern __shared__ float sm[];
  float* s_attn = sm;                 // 12288
  float* s_A    = sm + 12288;         // 8192
  float* s_W    = sm + 20480;         // 1536
  float* s_b    = sm + 22016;         // 12
  float* s_red  = sm + 22028;         // 192

  int i = blockIdx.x, tid = threadIdx.x;
  int lane = tid & 31, w = tid >> 5;
  for (int t = tid; t < 1536; t += 512) s_W[t] = Wp[t];
  if (tid < 12) s_b[tid] = bp[tid];
  __syncthreads();

  const float* xrow = x2d + (size_t)i * LL1 * PP;

  // ---- phase A: pair GEMM, warp per j-row, W in registers, no staging ----
  float wreg[4][12];
#pragma unroll
  for (int cc = 0; cc < 4; cc++)
#pragma unroll
    for (int h = 0; h < 12; h++) wreg[cc][h] = s_W[(lane * 4 + cc) * 12 + h];

  for (int j = w; j < 1024; j += 16) {
    float4 xv = *(const float4*)(xrow + (size_t)j * PP + lane * 4);
    float acc[12];
#pragma unroll
    for (int h = 0; h < 12; h++)
      acc[h] = xv.x * wreg[0][h] + xv.y * wreg[1][h] + xv.z * wreg[2][h] + xv.w * wreg[3][h];
#pragma unroll
    for (int o = 16; o; o >>= 1)
#pragma unroll
      for (int h = 0; h < 12; h++) acc[h] += __shfl_xor_sync(~0u, acc[h], o);
    if (lane < 12) s_attn[j * 12 + lane] = acc[lane];
  }
  __syncthreads();

  // combine pair bias with qk logits from g_Z
#pragma unroll
  for (int q = 0; q < 2; q++) {
    int j = q * 512 + tid;
#pragma unroll
    for (int h = 0; h < 12; h++)
      s_attn[j * 12 + h] = PAIR_W * (s_attn[j * 12 + h] + s_b[h]) + g_Z[(size_t)(h * LL1 + i) * LL1 + j];
  }
  __syncthreads();

  // ---- phase B: softmax over j for all 12 h ----
  float mx[12];
#pragma unroll
  for (int h = 0; h < 12; h++)
    mx[h] = fmaxf(s_attn[tid * 12 + h], s_attn[(tid + 512) * 12 + h]);
#pragma unroll
  for (int h = 0; h < 12; h++)
#pragma unroll
    for (int o = 16; o; o >>= 1) mx[h] = fmaxf(mx[h], __shfl_xor_sync(~0u, mx[h], o));
  if (lane == 0) {
#pragma unroll
    for (int h = 0; h < 12; h++) s_red[w * 12 + h] = mx[h];
  }
  __syncthreads();
  if (tid < 12) {
    float m = s_red[tid];
#pragma unroll
    for (int ww = 1; ww < 16; ww++) m = fmaxf(m, s_red[ww * 12 + tid]);
    s_red[tid] = m;
  }
  __syncthreads();
  float bm[12];
#pragma unroll
  for (int h = 0; h < 12; h++) bm[h] = s_red[h];
  __syncthreads();

  float sum_[12];
#pragma unroll
  for (int h = 0; h < 12; h++) sum_[h] = 0.f;
#pragma unroll
  for (int q = 0; q < 2; q++) {
    int j = q * 512 + tid;
#pragma unroll
    for (int h = 0; h < 12; h++) {
      float e = __expf(s_attn[j * 12 + h] - bm[h]);
      s_attn[j * 12 + h] = e;
      sum_[h] += e;
    }
  }
#pragma unroll
  for (int h = 0; h < 12; h++)
#pragma unroll
    for (int o = 16; o; o >>= 1) sum_[h] += __shfl_xor_sync(~0u, sum_[h], o);
  if (lane == 0) {
#pragma unroll
    for (int h = 0; h < 12; h++) s_red[w * 12 + h] = sum_[h];
  }
  __syncthreads();
  if (tid < 12) {
    float s = 0.f;
#pragma unroll
    for (int ww = 0; ww < 16; ww++) s += s_red[ww * 12 + tid];
    s_red[tid] = 1.f / s;
  }
  __syncthreads();
  float inv[12];
#pragma unroll
  for (int h = 0; h < 12; h++) inv[h] = s_red[h];
#pragma unroll
  for (int q = 0; q < 2; q++) {
    int j = q * 512 + tid;
#pragma unroll
    for (int h = 0; h < 12; h++) {
      float a = s_attn[j * 12 + h] * inv[h];
      s_attn[j * 12 + h] = a;
      g_Z[(size_t)(h * LL1 + i) * LL1 + j] = a;
    }
  }
  __syncthreads();

  // ---- phase C: r_2d = attn @ x2d. warp = (jg 0..3) x (hg 0..3), 3 h each --
  {
    int jg = w >> 2, hg = w & 3;         // jg: 256-j slab, hg: h = hg*3..hg*3+2
    float4 acc0 = {0,0,0,0}, acc1 = {0,0,0,0}, acc2 = {0,0,0,0};
    const float* xr = xrow + (size_t)(jg * 256) * PP + lane * 4;
#pragma unroll 4
    for (int jj = 0; jj < 256; jj++) {
      float4 xv = *(const float4*)(xr + (size_t)jj * PP);
      const float* ap = &s_attn[(jg * 256 + jj) * 12 + hg * 3];
      float a0 = ap[0], a1 = ap[1], a2 = ap[2];
      acc0.x += xv.x * a0; acc0.y += xv.y * a0; acc0.z += xv.z * a0; acc0.w += xv.w * a0;
      acc1.x += xv.x * a1; acc1.y += xv.y * a1; acc1.z += xv.z * a1; acc1.w += xv.w * a1;
      acc2.x += xv.x * a2; acc2.y += xv.y * a2; acc2.z += xv.z * a2; acc2.w += xv.w * a2;
    }
    float* pa = &s_A[w * 384];
    *(float4*)&pa[0 * 128 + lane * 4] = acc0;
    *(float4*)&pa[1 * 128 + lane * 4] = acc1;
    *(float4*)&pa[2 * 128 + lane * 4] = acc2;
  }
  __syncthreads();
  for (int t = tid; t < 1536; t += 512) {
    int h = t >> 7, c = t & 127;
    int hg = h / 3, hh = h % 3;
    float s = s_A[(0 * 4 + hg) * 384 + hh * 128 + c] + s_A[(1 * 4 + hg) * 384 + hh * 128 + c] +
              s_A[(2 * 4 + hg) * 384 + hh * 128 + c] + s_A[(3 * 4 + hg) * 384 + hh * 128 + c];
    g_feat[(size_t)i * FEAT + 576 + h * PP + c] = s;
  }
}

// ------------- K5: attn @ {v_s, vp} + inverse rigid + f_n -------------
__global__ void k_attnout(const float* __restrict__ rot, const float* __restrict__ trans) {
  int i0 = blockIdx.x * 8, h = blockIdx.y;
  int tid = threadIdx.x, lane = tid & 31, w = tid >> 5;
  __shared__ float s_a[8][1024];
  __shared__ float s_out[40][8];
  for (int idx = tid; idx < 8192; idx += 256) {
    int ii = idx >> 10, j = idx & 1023;
    s_a[ii][j] = g_Z[(size_t)(h * LL1 + i0 + ii) * LL1 + j];
  }
  __syncthreads();
  float acc[5][8];
#pragma unroll
  for (int c = 0; c < 5; c++)
#pragma unroll
    for (int ii = 0; ii < 8; ii++) acc[c][ii] = 0.f;
  const float* vptr[5];
#pragma unroll
  for (int c = 0; c < 5; c++) {
    int ch = w * 5 + c;
    vptr[c] = (ch < 16) ? &g_vT[(h * 16 + ch) * LL1] : &g_vpT[(h * 24 + ch - 16) * LL1];
  }
  for (int j = lane; j < 1024; j += 32) {
    float a[8];
#pragma unroll
    for (int ii = 0; ii < 8; ii++) a[ii] = s_a[ii][j];
#pragma unroll
    for (int c = 0; c < 5; c++) {
      float v = vptr[c][j];
#pragma unroll
      for (int ii = 0; ii < 8; ii++) acc[c][ii] += a[ii] * v;
    }
  }
#pragma unroll
  for (int c = 0; c < 5; c++)
#pragma unroll
    for (int ii = 0; ii < 8; ii++) {
      float s = acc[c][ii];
      for (int o = 16; o; o >>= 1) s += __shfl_xor_sync(~0u, s, o);
      if (lane == 0) s_out[w * 5 + c][ii] = s;
    }
  __syncthreads();
  if (tid < 128) {
    int ii = tid >> 4, c = tid & 15;
    g_feat[(size_t)(i0 + ii) * FEAT + h * 16 + c] = s_out[c][ii];
  } else if (tid < 192) {
    int p = tid - 128, ii = p >> 3, n = p & 7;
    int gi = i0 + ii;
    float R[9], t[3];
#pragma unroll
    for (int q = 0; q < 9; q++) R[q] = rot[gi * 9 + q];
#pragma unroll
    for (int q = 0; q < 3; q++) t[q] = trans[gi * 3 + q];
    float d0 = s_out[16 + n * 3 + 0][ii] - t[0];
    float d1 = s_out[16 + n * 3 + 1][ii] - t[1];
    float d2 = s_out[16 + n * 3 + 2][ii] - t[2];
    float lx = R[0] * d0 + R[3] * d1 + R[6] * d2;
    float ly = R[1] * d0 + R[4] * d1 + R[7] * d2;
    float lz = R[2] * d0 + R[5] * d1 + R[8] * d2;
    size_t base = (size_t)gi * FEAT;
    g_feat[base + 192 + 0 * 96 + h * 8 + n] = lx;
    g_feat[base + 192 + 1 * 96 + h * 8 + n] = ly;
    g_feat[base + 192 + 2 * 96 + h * 8 + n] = lz;
    g_feat[base + 480 + h * 8 + n] = sqrtf(lx * lx + ly * ly + lz * lz + 1e-8f);
  }
}

// ------------- K7: output GEMM feat[1024x2112] @ Wout[2112x384] -------------
__global__ void k_outgemm(const float* __restrict__ Wout, const float* __restrict__ bout,
                          float* __restrict__ out) {
  __shared__ float s_f[16][36];
  __shared__ float s_w[16][68];
  int tid = threadIdx.x;
  int tx = tid & 15, ty = tid >> 4;
  int i0 = blockIdx.x * 32, c0 = blockIdx.y * 64;
  float acc[2][4] = {};
  for (int k0 = 0; k0 < FEAT; k0 += 16) {
    __syncthreads();
    for (int idx = tid; idx < 512; idx += 256) {
      int il = idx >> 4, kk = idx & 15;
      s_f[kk][il] = g_feat[(size_t)(i0 + il) * FEAT + k0 + kk];
    }
    for (int idx = tid; idx < 1024; idx += 256) {
      int kk = idx >> 6, cl = idx & 63;
      s_w[kk][cl] = Wout[(size_t)(k0 + kk) * 384 + c0 + cl];
    }
    __syncthreads();
#pragma unroll
    for (int kk = 0; kk < 16; kk++) {
      float xv[2], wv[4];
#pragma unroll
      for (int r = 0; r < 2; r++) xv[r] = s_f[kk][ty * 2 + r];
#pragma unroll
      for (int cc = 0; cc < 4; cc++) wv[cc] = s_w[kk][tx * 4 + cc];
#pragma unroll
      for (int r = 0; r < 2; r++)
#pragma unroll
        for (int cc = 0; cc < 4; cc++) acc[r][cc] += xv[r] * wv[cc];
    }
  }
#pragma unroll
  for (int r = 0; r < 2; r++) {
    int ii = i0 + ty * 2 + r;
#pragma unroll
    for (int cc = 0; cc < 4; cc++) {
      int ccol = c0 + tx * 4 + cc;
      out[(size_t)ii * 384 + ccol] = acc[r][cc] + bout[ccol];
    }
  }
}

// ------------- launch -------------
extern "C" void kernel_launch(void* const* d_in, const int* in_sizes, int n_in,
                              void* d_out, int out_size) {
  (void)in_sizes; (void)n_in; (void)out_size;
  const float* x1d   = (const float*)d_in[0];
  const float* x2d   = (const float*)d_in[1];
  const float* rot   = (const float*)d_in[2];
  const float* trans = (const float*)d_in[3];
  // d_in[4] = mask (all true) — unused
  const float* Wq    = (const float*)d_in[5];
  const float* bq    = (const float*)d_in[6];
  const float* Wkv   = (const float*)d_in[7];
  const float* bkv   = (const float*)d_in[8];
  const float* Wqp   = (const float*)d_in[9];
  const float* bqp   = (const float*)d_in[10];
  const float* Wkvp  = (const float*)d_in[11];
  const float* bkvp  = (const float*)d_in[12];
  const float* Wpair = (const float*)d_in[13];
  const float* bpair = (const float*)d_in[14];
  const float* tpw   = (const float*)d_in[15];
  const float* Wout  = (const float*)d_in[16];
  const float* bout  = (const float*)d_in[17];
  float* out = (float*)d_out;

  cudaFuncSetAttribute(k_fuse, cudaFuncAttributeMaxDynamicSharedMemorySize, FUSE_SMEM_BYTES);

  k_projgemm<<<dim3(16, 9), 256>>>(x1d, Wq, Wkv, Wqp, Wkvp);
  k_post<<<1024, 256>>>(rot, trans, bq, bkv, bqp, bkvp);
  k_qk<<<dim3(128, 12), 256>>>(tpw);
  k_fuse<<<1024, 512, FUSE_SMEM_BYTES>>>(x2d, Wpair, bpair);
  k_attnout<<<dim3(128, 12), 256>>>(rot, trans);
  k_outgemm<<<dim3(32, 6), 256>>>(Wout, bout, out);
}

// round 6
// speedup vs baseline: 1.3591x; 1.3591x over previous
#include <cuda_runtime.h>
#include <math.h>

#define LL1 1024
#define CC 384
#define HH 12
#define PP 128

#define SCALAR_W 0.14433756729740643f
#define POINT_WC 0.13608276348795434f
#define PAIR_W   0.5773502691896258f

#define PROJ 1152
#define FEAT 2112

typedef unsigned long long ull;

__device__ __forceinline__ void fma2(ull& d, ull a, ull b) {
  asm("fma.rn.f32x2 %0, %1, %2, %0;" : "+l"(d) : "l"(a), "l"(b));
}
__device__ __forceinline__ void add2(ull& d, ull a) {
  asm("add.rn.f32x2 %0, %0, %1;" : "+l"(d) : "l"(a));
}
__device__ __forceinline__ ull pk(float lo, float hi) {
  ull r; asm("mov.b64 %0, {%1, %2};" : "=l"(r) : "f"(lo), "f"(hi)); return r;
}
__device__ __forceinline__ float2 upk(ull v) {
  float2 r; asm("mov.b64 {%0, %1}, %2;" : "=f"(r.x), "=f"(r.y) : "l"(v)); return r;
}

// ------------- static scratch -------------
__device__ float g_proj[LL1 * PROJ];
__device__ float g_q   [LL1 * 192];
__device__ float g_kT  [HH * 16 * LL1];
__device__ float g_vT  [HH * 16 * LL1];
__device__ float g_qp  [LL1 * 144];
__device__ float g_kpT [HH * 12 * LL1];
__device__ float g_vpT [HH * 24 * LL1];
__device__ float g_sqq [HH * LL1];
__device__ float g_sqk [HH * LL1];
__device__ float g_Z   [(size_t)HH * LL1 * LL1];
__device__ float g_feat[(size_t)LL1 * FEAT];

// ------------- K1: projection GEMM -------------
__device__ __forceinline__ float wload(int r, int gc, const float* Wq,
    const float* Wkv, const float* Wqp, const float* Wkvp) {
  if (gc < 192) return Wq[r * 192 + gc];
  if (gc < 576) return Wkv[r * 384 + (gc - 192)];
  if (gc < 720) return Wqp[r * 144 + (gc - 576)];
  return Wkvp[r * 432 + (gc - 720)];
}

__global__ void k_projgemm(const float* __restrict__ x1d, const float* __restrict__ Wq,
                           const float* __restrict__ Wkv, const float* __restrict__ Wqp,
                           const float* __restrict__ Wkvp) {
  __shared__ float s_x[16][68];
  __shared__ float s_w[16][128];
  int tid = threadIdx.x;
  int tx = tid & 15, ty = tid >> 4;
  int i0 = blockIdx.x * 64, c0 = blockIdx.y * 128;
  float acc[4][8] = {};
  for (int k0 = 0; k0 < CC; k0 += 16) {
    __syncthreads();
    for (int idx = tid; idx < 1024; idx += 256) {
      int il = idx >> 4, kk = idx & 15;
      s_x[kk][il] = x1d[(i0 + il) * CC + k0 + kk];
    }
    for (int idx = tid; idx < 2048; idx += 256) {
      int kk = idx >> 7, cl = idx & 127;
      s_w[kk][cl] = wload(k0 + kk, c0 + cl, Wq, Wkv, Wqp, Wkvp);
    }
    __syncthreads();
#pragma unroll
    for (int kk = 0; kk < 16; kk++) {
      float xv[4], wv[8];
#pragma unroll
      for (int r = 0; r < 4; r++) xv[r] = s_x[kk][ty * 4 + r];
#pragma unroll
      for (int c = 0; c < 8; c++) wv[c] = s_w[kk][tx * 8 + c];
#pragma unroll
      for (int r = 0; r < 4; r++)
#pragma unroll
        for (int c = 0; c < 8; c++) acc[r][c] += xv[r] * wv[c];
    }
  }
#pragma unroll
  for (int r = 0; r < 4; r++)
#pragma unroll
    for (int c = 0; c < 8; c++)
      g_proj[(size_t)(i0 + ty * 4 + r) * PROJ + c0 + tx * 8 + c] = acc[r][c];
}

// ------------- K2: bias/split/rigid/norms -------------
__global__ void k_post(const float* __restrict__ rot, const float* __restrict__ trans,
                       const float* __restrict__ bq, const float* __restrict__ bkv,
                       const float* __restrict__ bqp, const float* __restrict__ bkvp) {
  int i = blockIdx.x, tid = threadIdx.x;
  __shared__ float s_R[9], s_t[3], s_pt[96][3];
  if (tid < 9) s_R[tid] = rot[i * 9 + tid];
  else if (tid < 12) s_t[tid - 9] = trans[i * 3 + tid - 9];
  __syncthreads();
  const float* pr = &g_proj[(size_t)i * PROJ];
  for (int idx = tid; idx < 576; idx += 256) {
    if (idx < 192) {
      g_q[(size_t)i * 192 + idx] = (pr[idx] + bq[idx]) * SCALAR_W;
    } else {
      int m = idx - 192, hh = m >> 5, t = m & 31;
      float v = pr[idx] + bkv[m];
      if (t < 16) g_kT[(hh * 16 + t) * LL1 + i] = v;
      else        g_vT[(hh * 16 + t - 16) * LL1 + i] = v;
    }
  }
  for (int m = tid; m < 192; m += 256) {
    float p0, p1, p2;
    if (m < 48) {
      p0 = pr[576 + m] + bqp[m];
      p1 = pr[624 + m] + bqp[48 + m];
      p2 = pr[672 + m] + bqp[96 + m];
    } else {
      int mm = m - 48;
      p0 = pr[720 + mm] + bkvp[mm];
      p1 = pr[864 + mm] + bkvp[144 + mm];
      p2 = pr[1008 + mm] + bkvp[288 + mm];
    }
    float gx = s_R[0] * p0 + s_R[1] * p1 + s_R[2] * p2 + s_t[0];
    float gy = s_R[3] * p0 + s_R[4] * p1 + s_R[5] * p2 + s_t[1];
    float gz = s_R[6] * p0 + s_R[7] * p1 + s_R[8] * p2 + s_t[2];
    if (m < 48) {
      int hh = m >> 2, n = m & 3;
      size_t b = (size_t)i * 144 + hh * 12 + n * 3;
      g_qp[b] = gx; g_qp[b + 1] = gy; g_qp[b + 2] = gz;
      s_pt[m][0] = gx; s_pt[m][1] = gy; s_pt[m][2] = gz;
    } else {
      int mm = m - 48, hh = mm / 12, t = mm % 12;
      if (t < 4) {
        int b = (hh * 12 + t * 3) * LL1 + i;
        g_kpT[b] = gx; g_kpT[b + LL1] = gy; g_kpT[b + 2 * LL1] = gz;
        int sp = 48 + hh * 4 + t;
        s_pt[sp][0] = gx; s_pt[sp][1] = gy; s_pt[sp][2] = gz;
      } else {
        int b = (hh * 24 + (t - 4) * 3) * LL1 + i;
        g_vpT[b] = gx; g_vpT[b + LL1] = gy; g_vpT[b + 2 * LL1] = gz;
      }
    }
  }
  __syncthreads();
  if (tid < 24) {
    int hh = tid % 12; bool isq = tid < 12;
    float s = 0.f;
#pragma unroll
    for (int n = 0; n < 4; n++) {
      const float* p = s_pt[(isq ? 0 : 48) + hh * 4 + n];
      s += p[0] * p[0] + p[1] * p[1] + p[2] * p[2];
    }
    if (isq) g_sqq[hh * LL1 + i] = s;
    else     g_sqk[hh * LL1 + i] = s;
  }
}

// ------------- K3: qk + dist logits, i-tile 16, float4 over j -------------
__global__ void k_qk(const float* __restrict__ tpw) {
  int i0 = blockIdx.x * 16, h = blockIdx.y, tid = threadIdx.x; // 256 threads
  __shared__ float s_qT[16][16];   // [s][ii]
  __shared__ float s_qpT[12][16];  // [r][ii]
  __shared__ float s_sqq[16];
  __shared__ float s_pw;
  {
    int ii = tid >> 4, s = tid & 15;
    s_qT[s][ii] = g_q[(size_t)(i0 + ii) * 192 + h * 16 + s];
    if (tid < 192) { int r = tid % 12, ii2 = tid / 12; s_qpT[r][ii2] = g_qp[(size_t)(i0 + ii2) * 144 + h * 12 + r]; }
    if (tid < 16) s_sqq[tid] = g_sqq[h * LL1 + i0 + tid];
    if (tid == 0) {
      float x = tpw[h];
      s_pw = -0.5f * POINT_WC * (fmaxf(x, 0.f) + log1pf(expf(-fabsf(x))));
    }
  }
  __syncthreads();
  int j0 = tid * 4;
  float4 kv[16], kp[12];
#pragma unroll
  for (int s = 0; s < 16; s++) kv[s] = *(const float4*)&g_kT[(h * 16 + s) * LL1 + j0];
#pragma unroll
  for (int r = 0; r < 12; r++) kp[r] = *(const float4*)&g_kpT[(h * 12 + r) * LL1 + j0];
  float4 sqk = *(const float4*)&g_sqk[h * LL1 + j0];
  float pw = s_pw;
#pragma unroll
  for (int ii = 0; ii < 16; ii++) {
    float4 d = {0,0,0,0}, pq = {0,0,0,0};
#pragma unroll
    for (int s = 0; s < 16; s++) {
      float q = s_qT[s][ii];
      d.x += q * kv[s].x; d.y += q * kv[s].y; d.z += q * kv[s].z; d.w += q * kv[s].w;
    }
#pragma unroll
    for (int r = 0; r < 12; r++) {
      float q = s_qpT[r][ii];
      pq.x += q * kp[r].x; pq.y += q * kp[r].y; pq.z += q * kp[r].z; pq.w += q * kp[r].w;
    }
    float sq = s_sqq[ii];
    float4 o;
    o.x = d.x + pw * (sq + sqk.x - 2.f * pq.x);
    o.y = d.y + pw * (sq + sqk.y - 2.f * pq.y);
    o.z = d.z + pw * (sq + sqk.z - 2.f * pq.z);
    o.w = d.w + pw * (sq + sqk.w - 2.f * pq.w);
    *(float4*)&g_Z[((size_t)(h * LL1 + i0 + ii)) * LL1 + j0] = o;
  }
}

// ------------- K4: fused pair-bias + softmax + r_2d -------------
// smem floats: s_attn 12288 | s_x 9216 | s_W2 3072 | s_b 12 | s_red 192
#define FUSE_SMEM_FLOATS (12288 + 9216 + 3072 + 12 + 192)
#define FUSE_SMEM_BYTES (FUSE_SMEM_FLOATS * 4)

__global__ __launch_bounds__(512) void k_fuse(const float* __restrict__ x2d,
                                              const float* __restrict__ Wp,
                                              const float* __restrict__ bp) {
  extern __shared__ float sm[];
  float* s_attn = sm;                  // 12288
  float* s_x    = sm + 12288;          // 9216 (1024 rows x 9, scalar-stored)
  float* s_W2   = sm + 12288 + 9216;   // 3072 (128 c x 12 h x 2 dup)
  float* s_b    = s_W2 + 3072;         // 12
  float* s_red  = s_b + 12;            // 192

  int i = blockIdx.x, tid = threadIdx.x;
  int lane = tid & 31, w = tid >> 5;
  for (int t = tid; t < 1536; t += 512) {
    float v = Wp[t];
    s_W2[t * 2] = v; s_W2[t * 2 + 1] = v;
  }
  if (tid < 12) s_b[tid] = bp[tid];

  const float* xrow = x2d + (size_t)i * LL1 * PP;

  // ---- phase A: pair GEMM with staged x tile (stride-9 pad), f32x2 ----
  ull accA[12];
#pragma unroll
  for (int h = 0; h < 12; h++) accA[h] = 0ull;
  for (int k0 = 0; k0 < 128; k0 += 8) {
    __syncthreads();
#pragma unroll
    for (int p = 0; p < 4; p++) {
      int idx = p * 512 + tid;
      int r = idx >> 1, qq = idx & 1;
      float4 v = *(const float4*)(xrow + (size_t)r * PP + k0 + qq * 4);
      float* dst = &s_x[r * 9 + qq * 4];     // stride-9 rows: scalar stores (alignment)
      dst[0] = v.x; dst[1] = v.y; dst[2] = v.z; dst[3] = v.w;
    }
    __syncthreads();
#pragma unroll
    for (int kk = 0; kk < 8; kk++) {
      float a0 = s_x[tid * 9 + kk];
      float a1 = s_x[(tid + 512) * 9 + kk];
      ull a01 = pk(a0, a1);
      const ull* wp2 = (const ull*)&s_W2[(k0 + kk) * 24];
#pragma unroll
      for (int h = 0; h < 12; h++) fma2(accA[h], a01, wp2[h]);
    }
  }
  __syncthreads();
  // combine pair bias with qk logits
#pragma unroll
  for (int h = 0; h < 12; h++) {
    float2 pa = upk(accA[h]);
    s_attn[tid * 12 + h]         = PAIR_W * (pa.x + s_b[h]) + g_Z[(size_t)(h * LL1 + i) * LL1 + tid];
    s_attn[(tid + 512) * 12 + h] = PAIR_W * (pa.y + s_b[h]) + g_Z[(size_t)(h * LL1 + i) * LL1 + tid + 512];
  }
  __syncthreads();

  // ---- phase B: softmax ----
  float mx[12];
#pragma unroll
  for (int h = 0; h < 12; h++)
    mx[h] = fmaxf(s_attn[tid * 12 + h], s_attn[(tid + 512) * 12 + h]);
#pragma unroll
  for (int h = 0; h < 12; h++)
#pragma unroll
    for (int o = 16; o; o >>= 1) mx[h] = fmaxf(mx[h], __shfl_xor_sync(~0u, mx[h], o));
  if (lane == 0) {
#pragma unroll
    for (int h = 0; h < 12; h++) s_red[w * 12 + h] = mx[h];
  }
  __syncthreads();
  if (tid < 12) {
    float m = s_red[tid];
#pragma unroll
    for (int ww = 1; ww < 16; ww++) m = fmaxf(m, s_red[ww * 12 + tid]);
    s_red[tid] = m;
  }
  __syncthreads();
  float bm[12];
#pragma unroll
  for (int h = 0; h < 12; h++) bm[h] = s_red[h];
  __syncthreads();

  float sum_[12];
#pragma unroll
  for (int h = 0; h < 12; h++) sum_[h] = 0.f;
#pragma unroll
  for (int q = 0; q < 2; q++) {
    int j = q * 512 + tid;
#pragma unroll
    for (int h = 0; h < 12; h++) {
      float e = __expf(s_attn[j * 12 + h] - bm[h]);
      s_attn[j * 12 + h] = e;
      sum_[h] += e;
    }
  }
#pragma unroll
  for (int h = 0; h < 12; h++)
#pragma unroll
    for (int o = 16; o; o >>= 1) sum_[h] += __shfl_xor_sync(~0u, sum_[h], o);
  if (lane == 0) {
#pragma unroll
    for (int h = 0; h < 12; h++) s_red[w * 12 + h] = sum_[h];
  }
  __syncthreads();
  if (tid < 12) {
    float s = 0.f;
#pragma unroll
    for (int ww = 0; ww < 16; ww++) s += s_red[ww * 12 + tid];
    s_red[tid] = 1.f / s;
  }
  __syncthreads();
  float inv[12];
#pragma unroll
  for (int h = 0; h < 12; h++) inv[h] = s_red[h];
#pragma unroll
  for (int q = 0; q < 2; q++) {
    int j = q * 512 + tid;
#pragma unroll
    for (int h = 0; h < 12; h++) {
      float a = s_attn[j * 12 + h] * inv[h];
      s_attn[j * 12 + h] = a;
      g_Z[(size_t)(h * LL1 + i) * LL1 + j] = a;
    }
  }
  __syncthreads();

  // ---- phase C: r_2d. warp = 64-j slab, lane = c4, 12h packed acc ----
  ull acc[12][2];
#pragma unroll
  for (int h = 0; h < 12; h++) { acc[h][0] = 0ull; acc[h][1] = 0ull; }
  {
    int jbase = w * 64;
    const float* xr = xrow + (size_t)jbase * PP + lane * 4;
#pragma unroll 2
    for (int jj = 0; jj < 64; jj++) {
      float4 xv = *(const float4*)(xr + (size_t)jj * PP);
      ull x01 = pk(xv.x, xv.y), x23 = pk(xv.z, xv.w);
      const float* ap = &s_attn[(jbase + jj) * 12];
#pragma unroll
      for (int h = 0; h < 12; h++) {
        float a = ap[h];
        ull a2 = pk(a, a);
        fma2(acc[h][0], x01, a2);
        fma2(acc[h][1], x23, a2);
      }
    }
  }
  __syncthreads();
  // deterministic tree reduction over 16 warps, h-major conflict-free layout
  for (int step = 8; step >= 1; step >>= 1) {
    if (w >= step && w < 2 * step) {
      float4* dst = (float4*)s_attn;
#pragma unroll
      for (int h = 0; h < 12; h++) {
        float2 lo = upk(acc[h][0]), hi = upk(acc[h][1]);
        dst[h * (step * 32) + (w - step) * 32 + lane] = make_float4(lo.x, lo.y, hi.x, hi.y);
      }
    }
    __syncthreads();
    if (w < step) {
      const ull* src = (const ull*)s_attn;
#pragma unroll
      for (int h = 0; h < 12; h++) {
        add2(acc[h][0], src[(h * (step * 32) + w * 32 + lane) * 2]);
        add2(acc[h][1], src[(h * (step * 32) + w * 32 + lane) * 2 + 1]);
      }
    }
    __syncthreads();
  }
  if (w == 0) {
    size_t base = (size_t)i * FEAT + 576;
#pragma unroll
    for (int h = 0; h < 12; h++) {
      float2 lo = upk(acc[h][0]), hi = upk(acc[h][1]);
      *(float4*)&g_feat[base + h * PP + lane * 4] = make_float4(lo.x, lo.y, hi.x, hi.y);
    }
  }
}

// ------------- K5: attn @ {v_s, vp} + inverse rigid + f_n -------------
__global__ void k_attnout(const float* __restrict__ rot, const float* __restrict__ trans) {
  int i0 = blockIdx.x * 8, h = blockIdx.y;
  int tid = threadIdx.x, lane = tid & 31, w = tid >> 5;
  __shared__ float s_a[8][1024];
  __shared__ float s_out[40][8];
  for (int idx = tid; idx < 8192; idx += 256) {
    int ii = idx >> 10, j = idx & 1023;
    s_a[ii][j] = g_Z[(size_t)(h * LL1 + i0 + ii) * LL1 + j];
  }
  __syncthreads();
  float acc[5][8];
#pragma unroll
  for (int c = 0; c < 5; c++)
#pragma unroll
    for (int ii = 0; ii < 8; ii++) acc[c][ii] = 0.f;
  const float* vptr[5];
#pragma unroll
  for (int c = 0; c < 5; c++) {
    int ch = w * 5 + c;
    vptr[c] = (ch < 16) ? &g_vT[(h * 16 + ch) * LL1] : &g_vpT[(h * 24 + ch - 16) * LL1];
  }
  for (int j = lane; j < 1024; j += 32) {
    float a[8];
#pragma unroll
    for (int ii = 0; ii < 8; ii++) a[ii] = s_a[ii][j];
#pragma unroll
    for (int c = 0; c < 5; c++) {
      float v = vptr[c][j];
#pragma unroll
      for (int ii = 0; ii < 8; ii++) acc[c][ii] += a[ii] * v;
    }
  }
#pragma unroll
  for (int c = 0; c < 5; c++)
#pragma unroll
    for (int ii = 0; ii < 8; ii++) {
      float s = acc[c][ii];
      for (int o = 16; o; o >>= 1) s += __shfl_xor_sync(~0u, s, o);
      if (lane == 0) s_out[w * 5 + c][ii] = s;
    }
  __syncthreads();
  if (tid < 128) {
    int ii = tid >> 4, c = tid & 15;
    g_feat[(size_t)(i0 + ii) * FEAT + h * 16 + c] = s_out[c][ii];
  } else if (tid < 192) {
    int p = tid - 128, ii = p >> 3, n = p & 7;
    int gi = i0 + ii;
    float R[9], t[3];
#pragma unroll
    for (int q = 0; q < 9; q++) R[q] = rot[gi * 9 + q];
#pragma unroll
    for (int q = 0; q < 3; q++) t[q] = trans[gi * 3 + q];
    float d0 = s_out[16 + n * 3 + 0][ii] - t[0];
    float d1 = s_out[16 + n * 3 + 1][ii] - t[1];
    float d2 = s_out[16 + n * 3 + 2][ii] - t[2];
    float lx = R[0] * d0 + R[3] * d1 + R[6] * d2;
    float ly = R[1] * d0 + R[4] * d1 + R[7] * d2;
    float lz = R[2] * d0 + R[5] * d1 + R[8] * d2;
    size_t base = (size_t)gi * FEAT;
    g_feat[base + 192 + 0 * 96 + h * 8 + n] = lx;
    g_feat[base + 192 + 1 * 96 + h * 8 + n] = ly;
    g_feat[base + 192 + 2 * 96 + h * 8 + n] = lz;
    g_feat[base + 480 + h * 8 + n] = sqrtf(lx * lx + ly * ly + lz * lz + 1e-8f);
  }
}

// ------------- K7: output GEMM -------------
__global__ void k_outgemm(const float* __restrict__ Wout, const float* __restrict__ bout,
                          float* __restrict__ out) {
  __shared__ float s_f[16][36];
  __shared__ float s_w[16][68];
  int tid = threadIdx.x;
  int tx = tid & 15, ty = tid >> 4;
  int i0 = blockIdx.x * 32, c0 = blockIdx.y * 64;
  float acc[2][4] = {};
  for (int k0 = 0; k0 < FEAT; k0 += 16) {
    __syncthreads();
    for (int idx = tid; idx < 512; idx += 256) {
      int il = idx >> 4, kk = idx & 15;
      s_f[kk][il] = g_feat[(size_t)(i0 + il) * FEAT + k0 + kk];
    }
    for (int idx = tid; idx < 1024; idx += 256) {
      int kk = idx >> 6, cl = idx & 63;
      s_w[kk][cl] = Wout[(size_t)(k0 + kk) * 384 + c0 + cl];
    }
    __syncthreads();
#pragma unroll
    for (int kk = 0; kk < 16; kk++) {
      float xv[2], wv[4];
#pragma unroll
      for (int r = 0; r < 2; r++) xv[r] = s_f[kk][ty * 2 + r];
#pragma unroll
      for (int cc = 0; cc < 4; cc++) wv[cc] = s_w[kk][tx * 4 + cc];
#pragma unroll
      for (int r = 0; r < 2; r++)
#pragma unroll
        for (int cc = 0; cc < 4; cc++) acc[r][cc] += xv[r] * wv[cc];
    }
  }
#pragma unroll
  for (int r = 0; r < 2; r++) {
    int ii = i0 + ty * 2 + r;
#pragma unroll
    for (int cc = 0; cc < 4; cc++) {
      int ccol = c0 + tx * 4 + cc;
      out[(size_t)ii * 384 + ccol] = acc[r][cc] + bout[ccol];
    }
  }
}

// ------------- launch -------------
extern "C" void kernel_launch(void* const* d_in, const int* in_sizes, int n_in,
                              void* d_out, int out_size) {
  (void)in_sizes; (void)n_in; (void)out_size;
  const float* x1d   = (const float*)d_in[0];
  const float* x2d   = (const float*)d_in[1];
  const float* rot   = (const float*)d_in[2];
  const float* trans = (const float*)d_in[3];
  const float* Wq    = (const float*)d_in[5];
  const float* bq    = (const float*)d_in[6];
  const float* Wkv   = (const float*)d_in[7];
  const float* bkv   = (const float*)d_in[8];
  const float* Wqp   = (const float*)d_in[9];
  const float* bqp   = (const float*)d_in[10];
  const float* Wkvp  = (const float*)d_in[11];
  const float* bkvp  = (const float*)d_in[12];
  const float* Wpair = (const float*)d_in[13];
  const float* bpair = (const float*)d_in[14];
  const float* tpw   = (const float*)d_in[15];
  const float* Wout  = (const float*)d_in[16];
  const float* bout  = (const float*)d_in[17];
  float* out = (float*)d_out;

  cudaFuncSetAttribute(k_fuse, cudaFuncAttributeMaxDynamicSharedMemorySize, FUSE_SMEM_BYTES);

  k_projgemm<<<dim3(16, 9), 256>>>(x1d, Wq, Wkv, Wqp, Wkvp);
  k_post<<<1024, 256>>>(rot, trans, bq, bkv, bqp, bkvp);
  k_qk<<<dim3(64, 12), 256>>>(tpw);
  k_fuse<<<1024, 512, FUSE_SMEM_BYTES>>>(x2d, Wpair, bpair);
  k_attnout<<<dim3(128, 12), 256>>>(rot, trans);
  k_outgemm<<<dim3(32, 6), 256>>>(Wout, bout, out);
}

// round 7
// speedup vs baseline: 1.9816x; 1.4581x over previous
#include <cuda_runtime.h>
#include <math.h>

#define LL1 1024
#define CC 384
#define HH 12
#define PP 128

#define SCALAR_W 0.14433756729740643f
#define POINT_WC 0.13608276348795434f
#define PAIR_W   0.5773502691896258f

#define PROJ 1152
#define FEAT 2112

// ------------- static scratch -------------
__device__ float g_proj[LL1 * PROJ];
__device__ float g_q   [LL1 * 192];
__device__ float g_kT  [HH * 16 * LL1];
__device__ float g_vT  [HH * 16 * LL1];
__device__ float g_qp  [LL1 * 144];
__device__ float g_kpT [HH * 12 * LL1];
__device__ float g_vpT [HH * 24 * LL1];
__device__ float g_sqq [HH * LL1];
__device__ float g_sqk [HH * LL1];
__device__ float g_Z   [(size_t)HH * LL1 * LL1];  // logits -> (+pair) -> attn in place
__device__ float g_feat[(size_t)LL1 * FEAT];
__device__ float g_part[4 * LL1 * CC];

// ------------- K1: projection GEMM, 32x128 tiles -------------
__device__ __forceinline__ float wload(int r, int gc, const float* Wq,
    const float* Wkv, const float* Wqp, const float* Wkvp) {
  if (gc < 192) return Wq[r * 192 + gc];
  if (gc < 576) return Wkv[r * 384 + (gc - 192)];
  if (gc < 720) return Wqp[r * 144 + (gc - 576)];
  return Wkvp[r * 432 + (gc - 720)];
}

__global__ __launch_bounds__(256) void k_projgemm(const float* __restrict__ x1d,
    const float* __restrict__ Wq, const float* __restrict__ Wkv,
    const float* __restrict__ Wqp, const float* __restrict__ Wkvp) {
  __shared__ float s_x[16][36];
  __shared__ float s_w[16][128];
  int tid = threadIdx.x;
  int tx = tid & 15, ty = tid >> 4;
  int i0 = blockIdx.x * 32, c0 = blockIdx.y * 128;
  float acc[2][8] = {};
  for (int k0 = 0; k0 < CC; k0 += 16) {
    __syncthreads();
    for (int idx = tid; idx < 512; idx += 256) {
      int il = idx >> 4, kk = idx & 15;
      s_x[kk][il] = x1d[(i0 + il) * CC + k0 + kk];
    }
    for (int idx = tid; idx < 2048; idx += 256) {
      int kk = idx >> 7, cl = idx & 127;
      s_w[kk][cl] = wload(k0 + kk, c0 + cl, Wq, Wkv, Wqp, Wkvp);
    }
    __syncthreads();
#pragma unroll
    for (int kk = 0; kk < 16; kk++) {
      float xv[2], wv[8];
#pragma unroll
      for (int r = 0; r < 2; r++) xv[r] = s_x[kk][ty * 2 + r];
#pragma unroll
      for (int c = 0; c < 8; c++) wv[c] = s_w[kk][tx * 8 + c];
#pragma unroll
      for (int r = 0; r < 2; r++)
#pragma unroll
        for (int c = 0; c < 8; c++) acc[r][c] += xv[r] * wv[c];
    }
  }
#pragma unroll
  for (int r = 0; r < 2; r++)
#pragma unroll
    for (int c = 0; c < 8; c++)
      g_proj[(size_t)(i0 + ty * 2 + r) * PROJ + c0 + tx * 8 + c] = acc[r][c];
}

// ------------- K2: bias/split/rigid/norms -------------
__global__ void k_post(const float* __restrict__ rot, const float* __restrict__ trans,
                       const float* __restrict__ bq, const float* __restrict__ bkv,
                       const float* __restrict__ bqp, const float* __restrict__ bkvp) {
  int i = blockIdx.x, tid = threadIdx.x;
  __shared__ float s_R[9], s_t[3], s_pt[96][3];
  if (tid < 9) s_R[tid] = rot[i * 9 + tid];
  else if (tid < 12) s_t[tid - 9] = trans[i * 3 + tid - 9];
  __syncthreads();
  const float* pr = &g_proj[(size_t)i * PROJ];
  for (int idx = tid; idx < 576; idx += 256) {
    if (idx < 192) {
      g_q[(size_t)i * 192 + idx] = (pr[idx] + bq[idx]) * SCALAR_W;
    } else {
      int m = idx - 192, hh = m >> 5, t = m & 31;
      float v = pr[idx] + bkv[m];
      if (t < 16) g_kT[(hh * 16 + t) * LL1 + i] = v;
      else        g_vT[(hh * 16 + t - 16) * LL1 + i] = v;
    }
  }
  for (int m = tid; m < 192; m += 256) {
    float p0, p1, p2;
    if (m < 48) {
      p0 = pr[576 + m] + bqp[m];
      p1 = pr[624 + m] + bqp[48 + m];
      p2 = pr[672 + m] + bqp[96 + m];
    } else {
      int mm = m - 48;
      p0 = pr[720 + mm] + bkvp[mm];
      p1 = pr[864 + mm] + bkvp[144 + mm];
      p2 = pr[1008 + mm] + bkvp[288 + mm];
    }
    float gx = s_R[0] * p0 + s_R[1] * p1 + s_R[2] * p2 + s_t[0];
    float gy = s_R[3] * p0 + s_R[4] * p1 + s_R[5] * p2 + s_t[1];
    float gz = s_R[6] * p0 + s_R[7] * p1 + s_R[8] * p2 + s_t[2];
    if (m < 48) {
      int hh = m >> 2, n = m & 3;
      size_t b = (size_t)i * 144 + hh * 12 + n * 3;
      g_qp[b] = gx; g_qp[b + 1] = gy; g_qp[b + 2] = gz;
      s_pt[m][0] = gx; s_pt[m][1] = gy; s_pt[m][2] = gz;
    } else {
      int mm = m - 48, hh = mm / 12, t = mm % 12;
      if (t < 4) {
        int b = (hh * 12 + t * 3) * LL1 + i;
        g_kpT[b] = gx; g_kpT[b + LL1] = gy; g_kpT[b + 2 * LL1] = gz;
        int sp = 48 + hh * 4 + t;
        s_pt[sp][0] = gx; s_pt[sp][1] = gy; s_pt[sp][2] = gz;
      } else {
        int b = (hh * 24 + (t - 4) * 3) * LL1 + i;
        g_vpT[b] = gx; g_vpT[b + LL1] = gy; g_vpT[b + 2 * LL1] = gz;
      }
    }
  }
  __syncthreads();
  if (tid < 24) {
    int hh = tid % 12; bool isq = tid < 12;
    float s = 0.f;
#pragma unroll
    for (int n = 0; n < 4; n++) {
      const float* p = s_pt[(isq ? 0 : 48) + hh * 4 + n];
      s += p[0] * p[0] + p[1] * p[1] + p[2] * p[2];
    }
    if (isq) g_sqq[hh * LL1 + i] = s;
    else     g_sqk[hh * LL1 + i] = s;
  }
}

// ------------- K3: qk + dist logits -> g_Z -------------
__global__ void k_qk(const float* __restrict__ tpw) {
  int i0 = blockIdx.x * 16, h = blockIdx.y, tid = threadIdx.x;
  __shared__ float s_qT[16][16];
  __shared__ float s_qpT[12][16];
  __shared__ float s_sqq[16];
  __shared__ float s_pw;
  {
    int ii = tid >> 4, s = tid & 15;
    s_qT[s][ii] = g_q[(size_t)(i0 + ii) * 192 + h * 16 + s];
    if (tid < 192) { int r = tid % 12, ii2 = tid / 12; s_qpT[r][ii2] = g_qp[(size_t)(i0 + ii2) * 144 + h * 12 + r]; }
    if (tid < 16) s_sqq[tid] = g_sqq[h * LL1 + i0 + tid];
    if (tid == 0) {
      float x = tpw[h];
      s_pw = -0.5f * POINT_WC * (fmaxf(x, 0.f) + log1pf(expf(-fabsf(x))));
    }
  }
  __syncthreads();
  int j0 = tid * 4;
  float4 kv[16], kp[12];
#pragma unroll
  for (int s = 0; s < 16; s++) kv[s] = *(const float4*)&g_kT[(h * 16 + s) * LL1 + j0];
#pragma unroll
  for (int r = 0; r < 12; r++) kp[r] = *(const float4*)&g_kpT[(h * 12 + r) * LL1 + j0];
  float4 sqk = *(const float4*)&g_sqk[h * LL1 + j0];
  float pw = s_pw;
#pragma unroll
  for (int ii = 0; ii < 16; ii++) {
    float4 d = {0,0,0,0}, pq = {0,0,0,0};
#pragma unroll
    for (int s = 0; s < 16; s++) {
      float q = s_qT[s][ii];
      d.x += q * kv[s].x; d.y += q * kv[s].y; d.z += q * kv[s].z; d.w += q * kv[s].w;
    }
#pragma unroll
    for (int r = 0; r < 12; r++) {
      float q = s_qpT[r][ii];
      pq.x += q * kp[r].x; pq.y += q * kp[r].y; pq.z += q * kp[r].z; pq.w += q * kp[r].w;
    }
    float sq = s_sqq[ii];
    float4 o;
    o.x = d.x + pw * (sq + sqk.x - 2.f * pq.x);
    o.y = d.y + pw * (sq + sqk.y - 2.f * pq.y);
    o.z = d.z + pw * (sq + sqk.z - 2.f * pq.z);
    o.w = d.w + pw * (sq + sqk.w - 2.f * pq.w);
    *(float4*)&g_Z[((size_t)(h * LL1 + i0 + ii)) * LL1 + j0] = o;
  }
}

// ------------- K4: pair bias GEMM, added in place to g_Z -------------
// block = (i, j-half of 512). 256 threads, thread handles 2 j.
__global__ __launch_bounds__(256) void k_pairbias(const float* __restrict__ x2d,
    const float* __restrict__ Wp, const float* __restrict__ bp) {
  __shared__ float s_x[16 * 516];
  __shared__ float s_W[1536];
  __shared__ float s_b[12];
  int i = blockIdx.x, j0 = blockIdx.y * 512, tid = threadIdx.x;
  for (int t = tid; t < 1536; t += 256) s_W[t] = Wp[t];
  if (tid < 12) s_b[tid] = bp[tid];
  float acc0[12] = {}, acc1[12] = {};
  const float* xrow = x2d + ((size_t)i * LL1 + j0) * PP;
  for (int k0 = 0; k0 < 128; k0 += 16) {
    __syncthreads();
#pragma unroll
    for (int p = 0; p < 8; p++) {
      int idx = p * 256 + tid;
      int r = idx >> 2, qq = idx & 3;
      float4 v = *(const float4*)(xrow + (size_t)r * PP + k0 + qq * 4);
      s_x[(qq * 4 + 0) * 516 + r] = v.x;
      s_x[(qq * 4 + 1) * 516 + r] = v.y;
      s_x[(qq * 4 + 2) * 516 + r] = v.z;
      s_x[(qq * 4 + 3) * 516 + r] = v.w;
    }
    __syncthreads();
#pragma unroll
    for (int kk = 0; kk < 16; kk++) {
      float a0 = s_x[kk * 516 + tid];
      float a1 = s_x[kk * 516 + tid + 256];
      const float* wr = &s_W[(k0 + kk) * 12];
#pragma unroll
      for (int h = 0; h < 12; h++) {
        float wv = wr[h];
        acc0[h] += a0 * wv;
        acc1[h] += a1 * wv;
      }
    }
  }
#pragma unroll
  for (int h = 0; h < 12; h++) {
    float b = s_b[h];
    size_t base = ((size_t)h * LL1 + i) * LL1 + j0 + tid;
    g_Z[base]       += PAIR_W * (acc0[h] + b);
    g_Z[base + 256] += PAIR_W * (acc1[h] + b);
  }
}

// ------------- K5: softmax per (i,h), register-resident -------------
__global__ __launch_bounds__(256) void k_softmax() {
  int i = blockIdx.x, h = blockIdx.y, tid = threadIdx.x;
  int lane = tid & 31, w = tid >> 5;
  __shared__ float s_red[8];
  __shared__ float s_bc;
  float* zr = &g_Z[((size_t)h * LL1 + i) * LL1];
  float4 v = *(const float4*)&zr[tid * 4];
  float m = fmaxf(fmaxf(v.x, v.y), fmaxf(v.z, v.w));
#pragma unroll
  for (int o = 16; o; o >>= 1) m = fmaxf(m, __shfl_xor_sync(~0u, m, o));
  if (lane == 0) s_red[w] = m;
  __syncthreads();
  if (tid == 0) {
    float mm = s_red[0];
#pragma unroll
    for (int q = 1; q < 8; q++) mm = fmaxf(mm, s_red[q]);
    s_bc = mm;
  }
  __syncthreads();
  m = s_bc;
  float4 e;
  e.x = __expf(v.x - m); e.y = __expf(v.y - m);
  e.z = __expf(v.z - m); e.w = __expf(v.w - m);
  float s = e.x + e.y + e.z + e.w;
#pragma unroll
  for (int o = 16; o; o >>= 1) s += __shfl_xor_sync(~0u, s, o);
  if (lane == 0) s_red[w] = s;
  __syncthreads();
  if (tid == 0) {
    float ss = 0.f;
#pragma unroll
    for (int q = 0; q < 8; q++) ss += s_red[q];
    s_bc = 1.f / ss;
  }
  __syncthreads();
  float inv = s_bc;
  e.x *= inv; e.y *= inv; e.z *= inv; e.w *= inv;
  *(float4*)&zr[tid * 4] = e;
}

// ------------- K6: r_2d = attn @ x2d (block = i, no reductions) -------------
__global__ __launch_bounds__(256) void k_r2d(const float* __restrict__ x2d) {
  __shared__ float s_at[12][260];
  int i = blockIdx.x, tid = threadIdx.x;
  int c2 = (tid & 63) * 2, g = tid >> 6;  // g in 0..3 -> 3 heads each
  float acc[3][2] = {};
  for (int chunk = 0; chunk < 4; chunk++) {
    __syncthreads();
#pragma unroll
    for (int p = 0; p < 12; p++)
      s_at[p][tid] = g_Z[((size_t)p * LL1 + i) * LL1 + chunk * 256 + tid];
    __syncthreads();
    const float* xr = x2d + ((size_t)i * LL1 + chunk * 256) * PP + c2;
#pragma unroll 4
    for (int jj = 0; jj < 256; jj++) {
      float2 xv = *(const float2*)(xr + (size_t)jj * PP);
#pragma unroll
      for (int hh = 0; hh < 3; hh++) {
        float a = s_at[g * 3 + hh][jj];
        acc[hh][0] += a * xv.x;
        acc[hh][1] += a * xv.y;
      }
    }
  }
  size_t base = (size_t)i * FEAT + 576;
#pragma unroll
  for (int hh = 0; hh < 3; hh++) {
    int h = g * 3 + hh;
    g_feat[base + h * PP + c2]     = acc[hh][0];
    g_feat[base + h * PP + c2 + 1] = acc[hh][1];
  }
}

// ------------- K7: attn @ {v_s, vp} + inverse rigid + f_n -------------
__global__ void k_attnout(const float* __restrict__ rot, const float* __restrict__ trans) {
  int i0 = blockIdx.x * 8, h = blockIdx.y;
  int tid = threadIdx.x, lane = tid & 31, w = tid >> 5;
  __shared__ float s_a[8][1024];
  __shared__ float s_out[40][8];
  for (int idx = tid; idx < 8192; idx += 256) {
    int ii = idx >> 10, j = idx & 1023;
    s_a[ii][j] = g_Z[(size_t)(h * LL1 + i0 + ii) * LL1 + j];
  }
  __syncthreads();
  float acc[5][8];
#pragma unroll
  for (int c = 0; c < 5; c++)
#pragma unroll
    for (int ii = 0; ii < 8; ii++) acc[c][ii] = 0.f;
  const float* vptr[5];
#pragma unroll
  for (int c = 0; c < 5; c++) {
    int ch = w * 5 + c;
    vptr[c] = (ch < 16) ? &g_vT[(h * 16 + ch) * LL1] : &g_vpT[(h * 24 + ch - 16) * LL1];
  }
  for (int j = lane; j < 1024; j += 32) {
    float a[8];
#pragma unroll
    for (int ii = 0; ii < 8; ii++) a[ii] = s_a[ii][j];
#pragma unroll
    for (int c = 0; c < 5; c++) {
      float v = vptr[c][j];
#pragma unroll
      for (int ii = 0; ii < 8; ii++) acc[c][ii] += a[ii] * v;
    }
  }
#pragma unroll
  for (int c = 0; c < 5; c++)
#pragma unroll
    for (int ii = 0; ii < 8; ii++) {
      float s = acc[c][ii];
      for (int o = 16; o; o >>= 1) s += __shfl_xor_sync(~0u, s, o);
      if (lane == 0) s_out[w * 5 + c][ii] = s;
    }
  __syncthreads();
  if (tid < 128) {
    int ii = tid >> 4, c = tid & 15;
    g_feat[(size_t)(i0 + ii) * FEAT + h * 16 + c] = s_out[c][ii];
  } else if (tid < 192) {
    int p = tid - 128, ii = p >> 3, n = p & 7;
    int gi = i0 + ii;
    float R[9], t[3];
#pragma unroll
    for (int q = 0; q < 9; q++) R[q] = rot[gi * 9 + q];
#pragma unroll
    for (int q = 0; q < 3; q++) t[q] = trans[gi * 3 + q];
    float d0 = s_out[16 + n * 3 + 0][ii] - t[0];
    float d1 = s_out[16 + n * 3 + 1][ii] - t[1];
    float d2 = s_out[16 + n * 3 + 2][ii] - t[2];
    float lx = R[0] * d0 + R[3] * d1 + R[6] * d2;
    float ly = R[1] * d0 + R[4] * d1 + R[7] * d2;
    float lz = R[2] * d0 + R[5] * d1 + R[8] * d2;
    size_t base = (size_t)gi * FEAT;
    g_feat[base + 192 + 0 * 96 + h * 8 + n] = lx;
    g_feat[base + 192 + 1 * 96 + h * 8 + n] = ly;
    g_feat[base + 192 + 2 * 96 + h * 8 + n] = lz;
    g_feat[base + 480 + h * 8 + n] = sqrtf(lx * lx + ly * ly + lz * lz + 1e-8f);
  }
}

// ------------- K8: output GEMM, split-K x4 partials -------------
__global__ __launch_bounds__(256) void k_outpart(const float* __restrict__ Wout) {
  __shared__ float s_f[16][68];
  __shared__ float s_w[16][68];
  int tid = threadIdx.x;
  int tx = tid & 15, ty = tid >> 4;
  int i0 = blockIdx.x * 64, c0 = blockIdx.y * 64;
  int kbeg = blockIdx.z * 528, kend = kbeg + 528;
  float acc[4][4] = {};
  for (int k0 = kbeg; k0 < kend; k0 += 16) {
    __syncthreads();
    for (int idx = tid; idx < 1024; idx += 256) {
      int il = idx >> 4, kk = idx & 15;
      s_f[kk][il] = g_feat[(size_t)(i0 + il) * FEAT + k0 + kk];
    }
    for (int idx = tid; idx < 1024; idx += 256) {
      int kk = idx >> 6, cl = idx & 63;
      s_w[kk][cl] = Wout[(size_t)(k0 + kk) * CC + c0 + cl];
    }
    __syncthreads();
#pragma unroll
    for (int kk = 0; kk < 16; kk++) {
      float xv[4], wv[4];
#pragma unroll
      for (int r = 0; r < 4; r++) xv[r] = s_f[kk][ty * 4 + r];
#pragma unroll
      for (int c = 0; c < 4; c++) wv[c] = s_w[kk][tx * 4 + c];
#pragma unroll
      for (int r = 0; r < 4; r++)
#pragma unroll
        for (int c = 0; c < 4; c++) acc[r][c] += xv[r] * wv[c];
    }
  }
  float* part = &g_part[(size_t)blockIdx.z * LL1 * CC];
#pragma unroll
  for (int r = 0; r < 4; r++)
#pragma unroll
    for (int c = 0; c < 4; c++)
      part[(size_t)(i0 + ty * 4 + r) * CC + c0 + tx * 4 + c] = acc[r][c];
}

__global__ __launch_bounds__(256) void k_outadd(const float* __restrict__ bout,
                                                float* __restrict__ out) {
  int idx = blockIdx.x * 256 + threadIdx.x;
  float s = g_part[idx] + g_part[LL1 * CC + idx] + g_part[2 * LL1 * CC + idx] +
            g_part[3 * LL1 * CC + idx];
  out[idx] = s + bout[idx % CC];
}

// ------------- launch -------------
extern "C" void kernel_launch(void* const* d_in, const int* in_sizes, int n_in,
                              void* d_out, int out_size) {
  (void)in_sizes; (void)n_in; (void)out_size;
  const float* x1d   = (const float*)d_in[0];
  const float* x2d   = (const float*)d_in[1];
  const float* rot   = (const float*)d_in[2];
  const float* trans = (const float*)d_in[3];
  const float* Wq    = (const float*)d_in[5];
  const float* bq    = (const float*)d_in[6];
  const float* Wkv   = (const float*)d_in[7];
  const float* bkv   = (const float*)d_in[8];
  const float* Wqp   = (const float*)d_in[9];
  const float* bqp   = (const float*)d_in[10];
  const float* Wkvp  = (const float*)d_in[11];
  const float* bkvp  = (const float*)d_in[12];
  const float* Wpair = (const float*)d_in[13];
  const float* bpair = (const float*)d_in[14];
  const float* tpw   = (const float*)d_in[15];
  const float* Wout  = (const float*)d_in[16];
  const float* bout  = (const float*)d_in[17];
  float* out = (float*)d_out;

  k_projgemm<<<dim3(32, 9), 256>>>(x1d, Wq, Wkv, Wqp, Wkvp);
  k_post<<<1024, 256>>>(rot, trans, bq, bkv, bqp, bkvp);
  k_qk<<<dim3(64, 12), 256>>>(tpw);
  k_pairbias<<<dim3(1024, 2), 256>>>(x2d, Wpair, bpair);
  k_softmax<<<dim3(1024, 12), 256>>>();
  k_r2d<<<1024, 256>>>(x2d);
  k_attnout<<<dim3(128, 12), 256>>>(rot, trans);
  k_outpart<<<dim3(16, 6, 4), 256>>>(Wout);
  k_outadd<<<1536, 256>>>(bout, out);
}